// round 1
// baseline (speedup 1.0000x reference)
#include <cuda_runtime.h>
#include <cstdint>

// Problem constants (fixed shapes)
#define N_NODES 50000
#define N_EDGES 1600000
constexpr int F_IN  = 128;
constexpr int F_HID = 64;
constexpr int F_OUT = 40;
constexpr int K_CHEB = 4;

// ---------------------------------------------------------------------------
// Scratch (static __device__ arrays: allowed, no runtime allocation)
// ---------------------------------------------------------------------------
__device__ float g_deg[N_NODES];
__device__ float g_dis[N_NODES];
__device__ float g_diag[N_NODES];
__device__ int   g_cnt[N_NODES];
__device__ int   g_rowptr[N_NODES + 1];
__device__ int   g_cursor[N_NODES];
__device__ int   g_col[N_EDGES];
__device__ float g_w[N_EDGES];
// Layer buffers: Z1 = [T0|T1|T2|T3] at F=128 (row stride 512)
//                Z2 = [T0|T1|T2|T3] at F=64  (row stride 256)
__device__ float g_Z1[(size_t)N_NODES * (K_CHEB * F_IN)];
__device__ float g_Z2[(size_t)N_NODES * (K_CHEB * F_HID)];

// ---------------------------------------------------------------------------
// Preprocessing kernels
// ---------------------------------------------------------------------------
__global__ void k_zero_nodes() {
    int i = blockIdx.x * blockDim.x + threadIdx.x;
    if (i < N_NODES) { g_deg[i] = 0.f; g_cnt[i] = 0; }
}

__global__ void k_degree(const int* __restrict__ src, const int* __restrict__ dst,
                         const float* __restrict__ ew) {
    int e = blockIdx.x * blockDim.x + threadIdx.x;
    if (e < N_EDGES) {
        atomicAdd(&g_deg[src[e]], ew[e]);
        atomicAdd(&g_cnt[dst[e]], 1);
    }
}

__global__ void k_norm() {
    int i = blockIdx.x * blockDim.x + threadIdx.x;
    if (i < N_NODES) {
        float d = g_deg[i];
        g_dis[i]  = (d > 0.f) ? rsqrtf(fmaxf(d, 1e-12f)) : 0.f;
        g_diag[i] = (d > 0.f) ? 0.f : -1.f;
    }
}

// Exclusive prefix sum of g_cnt -> g_rowptr, also init g_cursor.
__global__ void k_scan() {
    __shared__ int part[1024];
    const int tid = threadIdx.x;
    const int CH = (N_NODES + 1023) / 1024;  // 49
    const int base = tid * CH;
    int s = 0;
    for (int j = 0; j < CH; j++) {
        int i = base + j;
        if (i < N_NODES) s += g_cnt[i];
    }
    part[tid] = s;
    __syncthreads();
    // Hillis-Steele inclusive scan over 1024 partials
    for (int off = 1; off < 1024; off <<= 1) {
        int v = (tid >= off) ? part[tid - off] : 0;
        __syncthreads();
        part[tid] += v;
        __syncthreads();
    }
    int run = (tid > 0) ? part[tid - 1] : 0;
    for (int j = 0; j < CH; j++) {
        int i = base + j;
        if (i < N_NODES) {
            g_rowptr[i] = run;
            g_cursor[i] = run;
            run += g_cnt[i];
        }
    }
    if (tid == 1023) g_rowptr[N_NODES] = part[1023];
}

__global__ void k_fill(const int* __restrict__ src, const int* __restrict__ dst,
                       const float* __restrict__ ew) {
    int e = blockIdx.x * blockDim.x + threadIdx.x;
    if (e < N_EDGES) {
        int s = src[e], d = dst[e];
        int pos = atomicAdd(&g_cursor[d], 1);
        g_col[pos] = s;
        g_w[pos] = -g_dis[s] * ew[e] * g_dis[d];
    }
}

// Copy x (N x 128, stride 128) into Z1 slice 0 (stride 512)
__global__ void k_copyx(const float* __restrict__ x) {
    int i = blockIdx.x * blockDim.x + threadIdx.x;  // over N*32 float4
    if (i < N_NODES * (F_IN / 4)) {
        int row = i >> 5;         // /32
        int q = i & 31;
        float* Z1 = g_Z1;
        ((float4*)(Z1 + (size_t)row * 512))[q] = ((const float4*)x)[i];
    }
}

// ---------------------------------------------------------------------------
// SpMM: out = L_hat @ in (one warp per row), optionally res = 2*acc - prev
// VEC = floats per lane (4 -> F=128, 2 -> F=64)
// ---------------------------------------------------------------------------
template <int VEC>
__global__ void k_spmm(const float* __restrict__ in, int si,
                       float* __restrict__ out, int so,
                       const float* __restrict__ prev, int sp) {
    const int lane = threadIdx.x & 31;
    const int row = (blockIdx.x * blockDim.x + threadIdx.x) >> 5;
    if (row >= N_NODES) return;

    const int beg = g_rowptr[row];
    const int end = g_rowptr[row + 1];

    float acc[VEC];
#pragma unroll
    for (int i = 0; i < VEC; i++) acc[i] = 0.f;

    for (int b = beg; b < end; b += 32) {
        const int e = b + lane;
        int c = 0;
        float w = 0.f;
        if (e < end) { c = g_col[e]; w = g_w[e]; }
        const int m = min(32, end - b);
        for (int j = 0; j < m; j++) {
            const int cj = __shfl_sync(0xffffffffu, c, j);
            const float wj = __shfl_sync(0xffffffffu, w, j);
            const float* p = in + (size_t)cj * si + lane * VEC;
            if constexpr (VEC == 4) {
                const float4 v = *(const float4*)p;
                acc[0] = fmaf(wj, v.x, acc[0]);
                acc[1] = fmaf(wj, v.y, acc[1]);
                acc[2] = fmaf(wj, v.z, acc[2]);
                acc[3] = fmaf(wj, v.w, acc[3]);
            } else {
                const float2 v = *(const float2*)p;
                acc[0] = fmaf(wj, v.x, acc[0]);
                acc[1] = fmaf(wj, v.y, acc[1]);
            }
        }
    }

    // diagonal term
    const float dg = g_diag[row];
    {
        const float* p = in + (size_t)row * si + lane * VEC;
        if constexpr (VEC == 4) {
            const float4 v = *(const float4*)p;
            acc[0] = fmaf(dg, v.x, acc[0]);
            acc[1] = fmaf(dg, v.y, acc[1]);
            acc[2] = fmaf(dg, v.z, acc[2]);
            acc[3] = fmaf(dg, v.w, acc[3]);
        } else {
            const float2 v = *(const float2*)p;
            acc[0] = fmaf(dg, v.x, acc[0]);
            acc[1] = fmaf(dg, v.y, acc[1]);
        }
    }

    float res[VEC];
    if (prev != nullptr) {
        const float* p = prev + (size_t)row * sp + lane * VEC;
        if constexpr (VEC == 4) {
            const float4 v = *(const float4*)p;
            res[0] = 2.f * acc[0] - v.x;
            res[1] = 2.f * acc[1] - v.y;
            res[2] = 2.f * acc[2] - v.z;
            res[3] = 2.f * acc[3] - v.w;
        } else {
            const float2 v = *(const float2*)p;
            res[0] = 2.f * acc[0] - v.x;
            res[1] = 2.f * acc[1] - v.y;
        }
    } else {
#pragma unroll
        for (int i = 0; i < VEC; i++) res[i] = acc[i];
    }

    float* po = out + (size_t)row * so + lane * VEC;
    if constexpr (VEC == 4) {
        *(float4*)po = make_float4(res[0], res[1], res[2], res[3]);
    } else {
        *(float2*)po = make_float2(res[0], res[1]);
    }
}

// ---------------------------------------------------------------------------
// GEMM: out[N x M] = A[N x KD] @ W[KD x M] + bias, optional ReLU.
// W entirely in SMEM. 512 threads, block tile 128 rows, thread tile 4x4.
// ---------------------------------------------------------------------------
template <int KD, int M, bool RELU>
__global__ void k_gemm(const float* __restrict__ A, int lda,
                       const float* __restrict__ W,
                       const float* __restrict__ bias,
                       float* __restrict__ out, int ldo) {
    constexpr int BM = 128, BK = 16;
    extern __shared__ float sh[];
    float* Bs = sh;              // KD*M
    float* As = sh + KD * M;     // BK*BM, layout As[k][r]

    const int tid = threadIdx.x;  // 512 threads

    for (int i = tid; i < KD * M / 4; i += blockDim.x)
        ((float4*)Bs)[i] = ((const float4*)W)[i];

    const int cx = tid & 15;      // 16 col groups of 4 cols
    const int ry = tid >> 4;      // 32 row groups of 4 rows
    const bool colok = (cx * 4) < M;

    const int ntiles = (N_NODES + BM - 1) / BM;
    __syncthreads();

    for (int tile = blockIdx.x; tile < ntiles; tile += gridDim.x) {
        const int row0 = tile * BM;
        float acc[4][4];
#pragma unroll
        for (int j = 0; j < 4; j++)
#pragma unroll
            for (int i = 0; i < 4; i++) acc[j][i] = 0.f;

        for (int k0 = 0; k0 < KD; k0 += BK) {
            // stage A tile: BM*BK/4 = 512 float4s, one per thread
            {
                const int r = tid >> 2;
                const int kk4 = tid & 3;
                const int row = row0 + r;
                float4 v = make_float4(0.f, 0.f, 0.f, 0.f);
                if (row < N_NODES)
                    v = *(const float4*)(A + (size_t)row * lda + k0 + kk4 * 4);
                As[(kk4 * 4 + 0) * BM + r] = v.x;
                As[(kk4 * 4 + 1) * BM + r] = v.y;
                As[(kk4 * 4 + 2) * BM + r] = v.z;
                As[(kk4 * 4 + 3) * BM + r] = v.w;
            }
            __syncthreads();
#pragma unroll
            for (int kk = 0; kk < BK; kk++) {
                float a[4];
#pragma unroll
                for (int j = 0; j < 4; j++) a[j] = As[kk * BM + ry * 4 + j];
                float4 bb = make_float4(0.f, 0.f, 0.f, 0.f);
                if (colok)
                    bb = *(const float4*)(Bs + (size_t)(k0 + kk) * M + cx * 4);
#pragma unroll
                for (int j = 0; j < 4; j++) {
                    acc[j][0] = fmaf(a[j], bb.x, acc[j][0]);
                    acc[j][1] = fmaf(a[j], bb.y, acc[j][1]);
                    acc[j][2] = fmaf(a[j], bb.z, acc[j][2]);
                    acc[j][3] = fmaf(a[j], bb.w, acc[j][3]);
                }
            }
            __syncthreads();
        }

        // epilogue
        const int col = cx * 4;
#pragma unroll
        for (int j = 0; j < 4; j++) {
            const int row = row0 + ry * 4 + j;
            if (row < N_NODES) {
#pragma unroll
                for (int i = 0; i < 4; i++) {
                    const int c = col + i;
                    if (c < M) {
                        float v = acc[j][i] + bias[c];
                        if (RELU) v = fmaxf(v, 0.f);
                        out[(size_t)row * ldo + c] = v;
                    }
                }
            }
        }
    }
}

// ---------------------------------------------------------------------------
// Launch
// ---------------------------------------------------------------------------
extern "C" void kernel_launch(void* const* d_in, const int* in_sizes, int n_in,
                              void* d_out, int out_size) {
    const float* x  = (const float*)d_in[0];
    const int*   ei = (const int*)d_in[1];
    const float* ew = (const float*)d_in[2];
    const float* W1 = (const float*)d_in[3];
    const float* b1 = (const float*)d_in[4];
    const float* W2 = (const float*)d_in[5];
    const float* b2 = (const float*)d_in[6];
    const int* src = ei;
    const int* dst = ei + N_EDGES;

    float *Z1, *Z2;
    cudaGetSymbolAddress((void**)&Z1, g_Z1);
    cudaGetSymbolAddress((void**)&Z2, g_Z2);

    const int smem1 = (512 * 64 + 128 * 16) * 4;   // 139264 B
    const int smem2 = (256 * 40 + 128 * 16) * 4;   // 49152 B
    cudaFuncSetAttribute((const void*)k_gemm<512, 64, true>,
                         cudaFuncAttributeMaxDynamicSharedMemorySize, smem1);
    cudaFuncSetAttribute((const void*)k_gemm<256, 40, false>,
                         cudaFuncAttributeMaxDynamicSharedMemorySize, smem2);

    const int ngrid = (N_NODES + 255) / 256;         // 196
    const int egrid = (N_EDGES + 255) / 256;         // 6250
    const int sgrid = (N_NODES * 32 + 255) / 256;    // 6250 (1 warp/row)
    const int cgrid = (N_NODES * (F_IN / 4) + 255) / 256;

    k_zero_nodes<<<ngrid, 256>>>();
    k_degree<<<egrid, 256>>>(src, dst, ew);
    k_norm<<<ngrid, 256>>>();
    k_scan<<<1, 1024>>>();
    k_fill<<<egrid, 256>>>(src, dst, ew);
    k_copyx<<<cgrid, 256>>>(x);

    // Layer 1: T1, T2, T3 at F=128 (row stride 512 within Z1)
    k_spmm<4><<<sgrid, 256>>>(Z1,       512, Z1 + 128, 512, nullptr,  0);
    k_spmm<4><<<sgrid, 256>>>(Z1 + 128, 512, Z1 + 256, 512, Z1,      512);
    k_spmm<4><<<sgrid, 256>>>(Z1 + 256, 512, Z1 + 384, 512, Z1 + 128, 512);

    // h = relu(Z1 @ W1 + b1) -> written directly into Z2 slice 0 (T0 of layer 2)
    k_gemm<512, 64, true><<<148, 512, smem1>>>(Z1, 512, W1, b1, Z2, 256);

    // Layer 2: T1, T2, T3 at F=64 (row stride 256 within Z2)
    k_spmm<2><<<sgrid, 256>>>(Z2,       256, Z2 + 64,  256, nullptr,  0);
    k_spmm<2><<<sgrid, 256>>>(Z2 + 64,  256, Z2 + 128, 256, Z2,      256);
    k_spmm<2><<<sgrid, 256>>>(Z2 + 128, 256, Z2 + 192, 256, Z2 + 64, 256);

    // out = Z2 @ W2 + b2
    k_gemm<256, 40, false><<<148, 512, smem2>>>(Z2, 256, W2, b2,
                                                (float*)d_out, 40);
}

// round 2
// speedup vs baseline: 1.0032x; 1.0032x over previous
#include <cuda_runtime.h>
#include <cstdint>

// Problem constants (fixed shapes)
#define N_NODES 50000
#define N_EDGES 1600000
constexpr int F_IN  = 128;
constexpr int F_HID = 64;
constexpr int F_OUT = 40;
constexpr int K_CHEB = 4;

// ---------------------------------------------------------------------------
// Scratch (static __device__ arrays: allowed, no runtime allocation)
// ---------------------------------------------------------------------------
__device__ float g_deg[N_NODES];
__device__ float g_dis[N_NODES];
__device__ float g_diag[N_NODES];
__device__ int   g_cnt[N_NODES];
__device__ int   g_rowptr[N_NODES + 1];
__device__ int   g_cursor[N_NODES];
__device__ int   g_col[N_EDGES];
__device__ float g_w[N_EDGES];
// Layer buffers: Z1 = [T0|T1|T2|T3] at F=128 (row stride 512)
//                Z2 = [T0|T1|T2|T3] at F=64  (row stride 256)
__device__ float g_Z1[(size_t)N_NODES * (K_CHEB * F_IN)];
__device__ float g_Z2[(size_t)N_NODES * (K_CHEB * F_HID)];

// ---------------------------------------------------------------------------
// Preprocessing kernels
// ---------------------------------------------------------------------------
__global__ void k_zero_nodes() {
    int i = blockIdx.x * blockDim.x + threadIdx.x;
    if (i < N_NODES) { g_deg[i] = 0.f; g_cnt[i] = 0; }
}

__global__ void k_degree(const int* __restrict__ src, const int* __restrict__ dst,
                         const float* __restrict__ ew) {
    int e = blockIdx.x * blockDim.x + threadIdx.x;
    if (e < N_EDGES) {
        atomicAdd(&g_deg[src[e]], ew[e]);
        atomicAdd(&g_cnt[dst[e]], 1);
    }
}

__global__ void k_norm() {
    int i = blockIdx.x * blockDim.x + threadIdx.x;
    if (i < N_NODES) {
        float d = g_deg[i];
        g_dis[i]  = (d > 0.f) ? rsqrtf(fmaxf(d, 1e-12f)) : 0.f;
        g_diag[i] = (d > 0.f) ? 0.f : -1.f;
    }
}

// Exclusive prefix sum of g_cnt -> g_rowptr, also init g_cursor.
__global__ void k_scan() {
    __shared__ int part[1024];
    const int tid = threadIdx.x;
    const int CH = (N_NODES + 1023) / 1024;  // 49
    const int base = tid * CH;
    int s = 0;
    for (int j = 0; j < CH; j++) {
        int i = base + j;
        if (i < N_NODES) s += g_cnt[i];
    }
    part[tid] = s;
    __syncthreads();
    // Hillis-Steele inclusive scan over 1024 partials
    for (int off = 1; off < 1024; off <<= 1) {
        int v = (tid >= off) ? part[tid - off] : 0;
        __syncthreads();
        part[tid] += v;
        __syncthreads();
    }
    int run = (tid > 0) ? part[tid - 1] : 0;
    for (int j = 0; j < CH; j++) {
        int i = base + j;
        if (i < N_NODES) {
            g_rowptr[i] = run;
            g_cursor[i] = run;
            run += g_cnt[i];
        }
    }
    if (tid == 1023) g_rowptr[N_NODES] = part[1023];
}

__global__ void k_fill(const int* __restrict__ src, const int* __restrict__ dst,
                       const float* __restrict__ ew) {
    int e = blockIdx.x * blockDim.x + threadIdx.x;
    if (e < N_EDGES) {
        int s = src[e], d = dst[e];
        int pos = atomicAdd(&g_cursor[d], 1);
        g_col[pos] = s;
        g_w[pos] = -g_dis[s] * ew[e] * g_dis[d];
    }
}

// Copy x (N x 128, stride 128) into Z1 slice 0 (stride 512)
__global__ void k_copyx(const float* __restrict__ x) {
    int i = blockIdx.x * blockDim.x + threadIdx.x;  // over N*32 float4
    if (i < N_NODES * (F_IN / 4)) {
        int row = i >> 5;         // /32
        int q = i & 31;
        float* Z1 = g_Z1;
        ((float4*)(Z1 + (size_t)row * 512))[q] = ((const float4*)x)[i];
    }
}

// ---------------------------------------------------------------------------
// SpMM: out = L_hat @ in (one warp per row), optionally res = 2*acc - prev
// VEC = floats per lane (4 -> F=128, 2 -> F=64)
// ---------------------------------------------------------------------------
template <int VEC>
__global__ void k_spmm(const float* __restrict__ in, int si,
                       float* __restrict__ out, int so,
                       const float* __restrict__ prev, int sp) {
    const int lane = threadIdx.x & 31;
    const int row = (blockIdx.x * blockDim.x + threadIdx.x) >> 5;
    if (row >= N_NODES) return;

    const int beg = g_rowptr[row];
    const int end = g_rowptr[row + 1];

    float acc[VEC];
#pragma unroll
    for (int i = 0; i < VEC; i++) acc[i] = 0.f;

    for (int b = beg; b < end; b += 32) {
        const int e = b + lane;
        int c = 0;
        float w = 0.f;
        if (e < end) { c = g_col[e]; w = g_w[e]; }
        const int m = min(32, end - b);
        for (int j = 0; j < m; j++) {
            const int cj = __shfl_sync(0xffffffffu, c, j);
            const float wj = __shfl_sync(0xffffffffu, w, j);
            const float* p = in + (size_t)cj * si + lane * VEC;
            if constexpr (VEC == 4) {
                const float4 v = *(const float4*)p;
                acc[0] = fmaf(wj, v.x, acc[0]);
                acc[1] = fmaf(wj, v.y, acc[1]);
                acc[2] = fmaf(wj, v.z, acc[2]);
                acc[3] = fmaf(wj, v.w, acc[3]);
            } else {
                const float2 v = *(const float2*)p;
                acc[0] = fmaf(wj, v.x, acc[0]);
                acc[1] = fmaf(wj, v.y, acc[1]);
            }
        }
    }

    // diagonal term
    const float dg = g_diag[row];
    {
        const float* p = in + (size_t)row * si + lane * VEC;
        if constexpr (VEC == 4) {
            const float4 v = *(const float4*)p;
            acc[0] = fmaf(dg, v.x, acc[0]);
            acc[1] = fmaf(dg, v.y, acc[1]);
            acc[2] = fmaf(dg, v.z, acc[2]);
            acc[3] = fmaf(dg, v.w, acc[3]);
        } else {
            const float2 v = *(const float2*)p;
            acc[0] = fmaf(dg, v.x, acc[0]);
            acc[1] = fmaf(dg, v.y, acc[1]);
        }
    }

    float res[VEC];
    if (prev != nullptr) {
        const float* p = prev + (size_t)row * sp + lane * VEC;
        if constexpr (VEC == 4) {
            const float4 v = *(const float4*)p;
            res[0] = 2.f * acc[0] - v.x;
            res[1] = 2.f * acc[1] - v.y;
            res[2] = 2.f * acc[2] - v.z;
            res[3] = 2.f * acc[3] - v.w;
        } else {
            const float2 v = *(const float2*)p;
            res[0] = 2.f * acc[0] - v.x;
            res[1] = 2.f * acc[1] - v.y;
        }
    } else {
#pragma unroll
        for (int i = 0; i < VEC; i++) res[i] = acc[i];
    }

    float* po = out + (size_t)row * so + lane * VEC;
    if constexpr (VEC == 4) {
        *(float4*)po = make_float4(res[0], res[1], res[2], res[3]);
    } else {
        *(float2*)po = make_float2(res[0], res[1]);
    }
}

// ---------------------------------------------------------------------------
// GEMM: out[N x M] = A[N x KD] @ W[KD x M] + bias, optional ReLU.
// W entirely in SMEM. 512 threads, block tile 128 rows, thread tile 4x4.
// ---------------------------------------------------------------------------
template <int KD, int M, bool RELU>
__global__ void k_gemm(const float* __restrict__ A, int lda,
                       const float* __restrict__ W,
                       const float* __restrict__ bias,
                       float* __restrict__ out, int ldo) {
    constexpr int BM = 128, BK = 16;
    extern __shared__ float sh[];
    float* Bs = sh;              // KD*M
    float* As = sh + KD * M;     // BK*BM, layout As[k][r]

    const int tid = threadIdx.x;  // 512 threads

    for (int i = tid; i < KD * M / 4; i += blockDim.x)
        ((float4*)Bs)[i] = ((const float4*)W)[i];

    const int cx = tid & 15;      // 16 col groups of 4 cols
    const int ry = tid >> 4;      // 32 row groups of 4 rows
    const bool colok = (cx * 4) < M;

    const int ntiles = (N_NODES + BM - 1) / BM;
    __syncthreads();

    for (int tile = blockIdx.x; tile < ntiles; tile += gridDim.x) {
        const int row0 = tile * BM;
        float acc[4][4];
#pragma unroll
        for (int j = 0; j < 4; j++)
#pragma unroll
            for (int i = 0; i < 4; i++) acc[j][i] = 0.f;

        for (int k0 = 0; k0 < KD; k0 += BK) {
            // stage A tile: BM*BK/4 = 512 float4s, one per thread
            {
                const int r = tid >> 2;
                const int kk4 = tid & 3;
                const int row = row0 + r;
                float4 v = make_float4(0.f, 0.f, 0.f, 0.f);
                if (row < N_NODES)
                    v = *(const float4*)(A + (size_t)row * lda + k0 + kk4 * 4);
                As[(kk4 * 4 + 0) * BM + r] = v.x;
                As[(kk4 * 4 + 1) * BM + r] = v.y;
                As[(kk4 * 4 + 2) * BM + r] = v.z;
                As[(kk4 * 4 + 3) * BM + r] = v.w;
            }
            __syncthreads();
#pragma unroll
            for (int kk = 0; kk < BK; kk++) {
                float a[4];
#pragma unroll
                for (int j = 0; j < 4; j++) a[j] = As[kk * BM + ry * 4 + j];
                float4 bb = make_float4(0.f, 0.f, 0.f, 0.f);
                if (colok)
                    bb = *(const float4*)(Bs + (size_t)(k0 + kk) * M + cx * 4);
#pragma unroll
                for (int j = 0; j < 4; j++) {
                    acc[j][0] = fmaf(a[j], bb.x, acc[j][0]);
                    acc[j][1] = fmaf(a[j], bb.y, acc[j][1]);
                    acc[j][2] = fmaf(a[j], bb.z, acc[j][2]);
                    acc[j][3] = fmaf(a[j], bb.w, acc[j][3]);
                }
            }
            __syncthreads();
        }

        // epilogue
        const int col = cx * 4;
#pragma unroll
        for (int j = 0; j < 4; j++) {
            const int row = row0 + ry * 4 + j;
            if (row < N_NODES) {
#pragma unroll
                for (int i = 0; i < 4; i++) {
                    const int c = col + i;
                    if (c < M) {
                        float v = acc[j][i] + bias[c];
                        if (RELU) v = fmaxf(v, 0.f);
                        out[(size_t)row * ldo + c] = v;
                    }
                }
            }
        }
    }
}

// ---------------------------------------------------------------------------
// Launch
// ---------------------------------------------------------------------------
extern "C" void kernel_launch(void* const* d_in, const int* in_sizes, int n_in,
                              void* d_out, int out_size) {
    const float* x  = (const float*)d_in[0];
    const int*   ei = (const int*)d_in[1];
    const float* ew = (const float*)d_in[2];
    const float* W1 = (const float*)d_in[3];
    const float* b1 = (const float*)d_in[4];
    const float* W2 = (const float*)d_in[5];
    const float* b2 = (const float*)d_in[6];
    const int* src = ei;
    const int* dst = ei + N_EDGES;

    float *Z1, *Z2;
    cudaGetSymbolAddress((void**)&Z1, g_Z1);
    cudaGetSymbolAddress((void**)&Z2, g_Z2);

    const int smem1 = (512 * 64 + 128 * 16) * 4;   // 139264 B
    const int smem2 = (256 * 40 + 128 * 16) * 4;   // 49152 B
    cudaFuncSetAttribute((const void*)k_gemm<512, 64, true>,
                         cudaFuncAttributeMaxDynamicSharedMemorySize, smem1);
    cudaFuncSetAttribute((const void*)k_gemm<256, 40, false>,
                         cudaFuncAttributeMaxDynamicSharedMemorySize, smem2);

    const int ngrid = (N_NODES + 255) / 256;         // 196
    const int egrid = (N_EDGES + 255) / 256;         // 6250
    const int sgrid = (N_NODES * 32 + 255) / 256;    // 6250 (1 warp/row)
    const int cgrid = (N_NODES * (F_IN / 4) + 255) / 256;

    k_zero_nodes<<<ngrid, 256>>>();
    k_degree<<<egrid, 256>>>(src, dst, ew);
    k_norm<<<ngrid, 256>>>();
    k_scan<<<1, 1024>>>();
    k_fill<<<egrid, 256>>>(src, dst, ew);
    k_copyx<<<cgrid, 256>>>(x);

    // Layer 1: T1, T2, T3 at F=128 (row stride 512 within Z1)
    k_spmm<4><<<sgrid, 256>>>(Z1,       512, Z1 + 128, 512, nullptr,  0);
    k_spmm<4><<<sgrid, 256>>>(Z1 + 128, 512, Z1 + 256, 512, Z1,      512);
    k_spmm<4><<<sgrid, 256>>>(Z1 + 256, 512, Z1 + 384, 512, Z1 + 128, 512);

    // h = relu(Z1 @ W1 + b1) -> written directly into Z2 slice 0 (T0 of layer 2)
    k_gemm<512, 64, true><<<148, 512, smem1>>>(Z1, 512, W1, b1, Z2, 256);

    // Layer 2: T1, T2, T3 at F=64 (row stride 256 within Z2)
    k_spmm<2><<<sgrid, 256>>>(Z2,       256, Z2 + 64,  256, nullptr,  0);
    k_spmm<2><<<sgrid, 256>>>(Z2 + 64,  256, Z2 + 128, 256, Z2,      256);
    k_spmm<2><<<sgrid, 256>>>(Z2 + 128, 256, Z2 + 192, 256, Z2 + 64, 256);

    // out = Z2 @ W2 + b2
    k_gemm<256, 40, false><<<148, 512, smem2>>>(Z2, 256, W2, b2,
                                                (float*)d_out, 40);
}

// round 3
// speedup vs baseline: 1.1761x; 1.1724x over previous
#include <cuda_runtime.h>
#include <cstdint>

// Problem constants (fixed shapes)
#define N_NODES 50000
#define N_EDGES 1600000
constexpr int F_IN  = 128;
constexpr int F_HID = 64;
constexpr int F_OUT = 40;
constexpr int K_CHEB = 4;

constexpr int SCAN_BS = 512;
constexpr int SCAN_NB = (N_NODES + SCAN_BS - 1) / SCAN_BS;  // 98

// ---------------------------------------------------------------------------
// Scratch
// ---------------------------------------------------------------------------
__device__ float g_deg[N_NODES];
__device__ float g_dis[N_NODES];
__device__ float g_diag[N_NODES];
__device__ int   g_cnt[N_NODES];
__device__ int   g_rowptr[N_NODES + 1];
__device__ int   g_cursor[N_NODES];
__device__ int   g_col[N_EDGES];
__device__ float g_w[N_EDGES];
__device__ int   g_bsum[SCAN_NB];
__device__ int   g_boff[SCAN_NB];
// Layer buffers: Z1 = [T0|T1|T2|T3] at F=128 (row stride 512)
//                Z2 = [T0|T1|T2|T3] at F=64  (row stride 256)
__device__ float g_Z1[(size_t)N_NODES * (K_CHEB * F_IN)];
__device__ float g_Z2[(size_t)N_NODES * (K_CHEB * F_HID)];

// ---------------------------------------------------------------------------
// Preprocessing
// ---------------------------------------------------------------------------
__global__ void k_zero_nodes() {
    int i = blockIdx.x * blockDim.x + threadIdx.x;
    if (i < N_NODES) { g_deg[i] = 0.f; g_cnt[i] = 0; }
}

__global__ void k_degree(const int* __restrict__ src, const int* __restrict__ dst,
                         const float* __restrict__ ew) {
    int e = blockIdx.x * blockDim.x + threadIdx.x;
    if (e < N_EDGES) {
        atomicAdd(&g_deg[src[e]], ew[e]);
        atomicAdd(&g_cnt[dst[e]], 1);
    }
}

__global__ void k_norm() {
    int i = blockIdx.x * blockDim.x + threadIdx.x;
    if (i < N_NODES) {
        float d = g_deg[i];
        g_dis[i]  = (d > 0.f) ? rsqrtf(fmaxf(d, 1e-12f)) : 0.f;
        g_diag[i] = (d > 0.f) ? 0.f : -1.f;
    }
}

// ---- 3-phase scan of g_cnt -> g_rowptr (exclusive), g_cursor ----
__global__ void k_scan1() {  // per-block sums
    __shared__ int ws[SCAN_BS / 32];
    const int tid = threadIdx.x;
    const int i = blockIdx.x * SCAN_BS + tid;
    int v = (i < N_NODES) ? g_cnt[i] : 0;
#pragma unroll
    for (int off = 16; off > 0; off >>= 1)
        v += __shfl_down_sync(0xffffffffu, v, off);
    if ((tid & 31) == 0) ws[tid >> 5] = v;
    __syncthreads();
    if (tid < SCAN_BS / 32) {
        int s = ws[tid];
#pragma unroll
        for (int off = SCAN_BS / 64; off > 0; off >>= 1)
            s += __shfl_down_sync(0xffffffffu, s, off);
        if (tid == 0) g_bsum[blockIdx.x] = s;
    }
}

__global__ void k_scan2() {  // scan 98 partials in one block of 128
    __shared__ int sm[128];
    const int tid = threadIdx.x;
    int v = (tid < SCAN_NB) ? g_bsum[tid] : 0;
    sm[tid] = v;
    __syncthreads();
#pragma unroll
    for (int off = 1; off < 128; off <<= 1) {
        int y = (tid >= off) ? sm[tid - off] : 0;
        __syncthreads();
        sm[tid] += y;
        __syncthreads();
    }
    if (tid < SCAN_NB) g_boff[tid] = sm[tid] - v;  // exclusive
    if (tid == 127) g_rowptr[N_NODES] = sm[127];   // total
}

__global__ void k_scan3() {  // block-wide exclusive scan + offset
    __shared__ int ws[SCAN_BS / 32];
    const int tid = threadIdx.x;
    const int lane = tid & 31;
    const int wid = tid >> 5;
    const int i = blockIdx.x * SCAN_BS + tid;
    int v = (i < N_NODES) ? g_cnt[i] : 0;
    int x = v;
#pragma unroll
    for (int off = 1; off < 32; off <<= 1) {
        int y = __shfl_up_sync(0xffffffffu, x, off);
        if (lane >= off) x += y;
    }
    if (lane == 31) ws[wid] = x;
    __syncthreads();
    if (wid == 0) {
        int s = (lane < SCAN_BS / 32) ? ws[lane] : 0;
#pragma unroll
        for (int off = 1; off < SCAN_BS / 32; off <<= 1) {
            int y = __shfl_up_sync(0xffffffffu, s, off);
            if (lane >= off) s += y;
        }
        if (lane < SCAN_BS / 32) ws[lane] = s;
    }
    __syncthreads();
    int excl = x - v + ((wid > 0) ? ws[wid - 1] : 0) + g_boff[blockIdx.x];
    if (i < N_NODES) { g_rowptr[i] = excl; g_cursor[i] = excl; }
}

__global__ void k_fill(const int* __restrict__ src, const int* __restrict__ dst,
                       const float* __restrict__ ew) {
    int e = blockIdx.x * blockDim.x + threadIdx.x;
    if (e < N_EDGES) {
        int s = src[e], d = dst[e];
        int pos = atomicAdd(&g_cursor[d], 1);
        g_col[pos] = s;
        g_w[pos] = -g_dis[s] * ew[e] * g_dis[d];
    }
}

// ---------------------------------------------------------------------------
// SpMM: out = L_hat @ in (one warp per row), optionally res = 2*acc - prev.
// No shuffles: all lanes load the same col/w scalar (L1 broadcast), inner
// loop unrolled x4 so 4 independent row gathers are in flight per warp.
// VEC = floats per lane (4 -> F=128, 2 -> F=64).
// copy0 != nullptr: also store in[row] slice to copy0 (stride sc).
// ---------------------------------------------------------------------------
template <int VEC>
__device__ __forceinline__ void vload(float (&v)[VEC], const float* __restrict__ p) {
    if constexpr (VEC == 4) {
        const float4 t = *(const float4*)p;
        v[0] = t.x; v[1] = t.y; v[2] = t.z; v[3] = t.w;
    } else {
        const float2 t = *(const float2*)p;
        v[0] = t.x; v[1] = t.y;
    }
}

template <int VEC>
__global__ __launch_bounds__(256) void k_spmm(
        const float* __restrict__ in, int si,
        float* __restrict__ out, int so,
        const float* __restrict__ prev, int sp,
        float* __restrict__ copy0, int sc) {
    const int lane = threadIdx.x & 31;
    const int row = (blockIdx.x * blockDim.x + threadIdx.x) >> 5;
    if (row >= N_NODES) return;

    const int beg = __ldg(&g_rowptr[row]);
    const int end = __ldg(&g_rowptr[row + 1]);
    const int lv = lane * VEC;

    float acc[VEC];
#pragma unroll
    for (int i = 0; i < VEC; i++) acc[i] = 0.f;

    int e = beg;
    for (; e + 4 <= end; e += 4) {
        const int c0 = __ldg(&g_col[e + 0]);
        const int c1 = __ldg(&g_col[e + 1]);
        const int c2 = __ldg(&g_col[e + 2]);
        const int c3 = __ldg(&g_col[e + 3]);
        const float w0 = __ldg(&g_w[e + 0]);
        const float w1 = __ldg(&g_w[e + 1]);
        const float w2 = __ldg(&g_w[e + 2]);
        const float w3 = __ldg(&g_w[e + 3]);
        float v0[VEC], v1[VEC], v2[VEC], v3[VEC];
        vload<VEC>(v0, in + (size_t)c0 * si + lv);
        vload<VEC>(v1, in + (size_t)c1 * si + lv);
        vload<VEC>(v2, in + (size_t)c2 * si + lv);
        vload<VEC>(v3, in + (size_t)c3 * si + lv);
#pragma unroll
        for (int i = 0; i < VEC; i++) {
            acc[i] = fmaf(w0, v0[i], acc[i]);
            acc[i] = fmaf(w1, v1[i], acc[i]);
            acc[i] = fmaf(w2, v2[i], acc[i]);
            acc[i] = fmaf(w3, v3[i], acc[i]);
        }
    }
    for (; e < end; e++) {
        const int c = __ldg(&g_col[e]);
        const float w = __ldg(&g_w[e]);
        float v[VEC];
        vload<VEC>(v, in + (size_t)c * si + lv);
#pragma unroll
        for (int i = 0; i < VEC; i++) acc[i] = fmaf(w, v[i], acc[i]);
    }

    // diagonal term (also the source for copy0)
    const float dg = g_diag[row];
    float vd[VEC];
    vload<VEC>(vd, in + (size_t)row * si + lv);
#pragma unroll
    for (int i = 0; i < VEC; i++) acc[i] = fmaf(dg, vd[i], acc[i]);

    if (copy0 != nullptr) {
        float* pc = copy0 + (size_t)row * sc + lv;
        if constexpr (VEC == 4)
            *(float4*)pc = make_float4(vd[0], vd[1], vd[2], vd[3]);
        else
            *(float2*)pc = make_float2(vd[0], vd[1]);
    }

    float res[VEC];
    if (prev != nullptr) {
        float vp[VEC];
        vload<VEC>(vp, prev + (size_t)row * sp + lv);
#pragma unroll
        for (int i = 0; i < VEC; i++) res[i] = 2.f * acc[i] - vp[i];
    } else {
#pragma unroll
        for (int i = 0; i < VEC; i++) res[i] = acc[i];
    }

    float* po = out + (size_t)row * so + lv;
    if constexpr (VEC == 4)
        *(float4*)po = make_float4(res[0], res[1], res[2], res[3]);
    else
        *(float2*)po = make_float2(res[0], res[1]);
}

// ---------------------------------------------------------------------------
// GEMM: out[N x M] = A[N x KD] @ W[KD x M] + bias, optional ReLU.
// W entirely in SMEM. 512 threads, block tile 128 rows, thread tile 4x4.
// ---------------------------------------------------------------------------
template <int KD, int M, bool RELU>
__global__ void k_gemm(const float* __restrict__ A, int lda,
                       const float* __restrict__ W,
                       const float* __restrict__ bias,
                       float* __restrict__ out, int ldo) {
    constexpr int BM = 128, BK = 16;
    extern __shared__ float sh[];
    float* Bs = sh;              // KD*M
    float* As = sh + KD * M;     // BK*BM, layout As[k][r]

    const int tid = threadIdx.x;  // 512 threads

    for (int i = tid; i < KD * M / 4; i += blockDim.x)
        ((float4*)Bs)[i] = ((const float4*)W)[i];

    const int cx = tid & 15;      // 16 col groups of 4 cols
    const int ry = tid >> 4;      // 32 row groups of 4 rows
    const bool colok = (cx * 4) < M;

    const int ntiles = (N_NODES + BM - 1) / BM;
    __syncthreads();

    for (int tile = blockIdx.x; tile < ntiles; tile += gridDim.x) {
        const int row0 = tile * BM;
        float acc[4][4];
#pragma unroll
        for (int j = 0; j < 4; j++)
#pragma unroll
            for (int i = 0; i < 4; i++) acc[j][i] = 0.f;

        for (int k0 = 0; k0 < KD; k0 += BK) {
            {
                const int r = tid >> 2;
                const int kk4 = tid & 3;
                const int row = row0 + r;
                float4 v = make_float4(0.f, 0.f, 0.f, 0.f);
                if (row < N_NODES)
                    v = *(const float4*)(A + (size_t)row * lda + k0 + kk4 * 4);
                As[(kk4 * 4 + 0) * BM + r] = v.x;
                As[(kk4 * 4 + 1) * BM + r] = v.y;
                As[(kk4 * 4 + 2) * BM + r] = v.z;
                As[(kk4 * 4 + 3) * BM + r] = v.w;
            }
            __syncthreads();
#pragma unroll
            for (int kk = 0; kk < BK; kk++) {
                float a[4];
#pragma unroll
                for (int j = 0; j < 4; j++) a[j] = As[kk * BM + ry * 4 + j];
                float4 bb = make_float4(0.f, 0.f, 0.f, 0.f);
                if (colok)
                    bb = *(const float4*)(Bs + (size_t)(k0 + kk) * M + cx * 4);
#pragma unroll
                for (int j = 0; j < 4; j++) {
                    acc[j][0] = fmaf(a[j], bb.x, acc[j][0]);
                    acc[j][1] = fmaf(a[j], bb.y, acc[j][1]);
                    acc[j][2] = fmaf(a[j], bb.z, acc[j][2]);
                    acc[j][3] = fmaf(a[j], bb.w, acc[j][3]);
                }
            }
            __syncthreads();
        }

        const int col = cx * 4;
#pragma unroll
        for (int j = 0; j < 4; j++) {
            const int row = row0 + ry * 4 + j;
            if (row < N_NODES) {
#pragma unroll
                for (int i = 0; i < 4; i++) {
                    const int c = col + i;
                    if (c < M) {
                        float v = acc[j][i] + bias[c];
                        if (RELU) v = fmaxf(v, 0.f);
                        out[(size_t)row * ldo + c] = v;
                    }
                }
            }
        }
    }
}

// ---------------------------------------------------------------------------
// Launch
// ---------------------------------------------------------------------------
extern "C" void kernel_launch(void* const* d_in, const int* in_sizes, int n_in,
                              void* d_out, int out_size) {
    const float* x  = (const float*)d_in[0];
    const int*   ei = (const int*)d_in[1];
    const float* ew = (const float*)d_in[2];
    const float* W1 = (const float*)d_in[3];
    const float* b1 = (const float*)d_in[4];
    const float* W2 = (const float*)d_in[5];
    const float* b2 = (const float*)d_in[6];
    const int* src = ei;
    const int* dst = ei + N_EDGES;

    float *Z1, *Z2;
    cudaGetSymbolAddress((void**)&Z1, g_Z1);
    cudaGetSymbolAddress((void**)&Z2, g_Z2);

    const int smem1 = (512 * 64 + 128 * 16) * 4;   // 139264 B
    const int smem2 = (256 * 40 + 128 * 16) * 4;   // 49152 B
    cudaFuncSetAttribute((const void*)k_gemm<512, 64, true>,
                         cudaFuncAttributeMaxDynamicSharedMemorySize, smem1);
    cudaFuncSetAttribute((const void*)k_gemm<256, 40, false>,
                         cudaFuncAttributeMaxDynamicSharedMemorySize, smem2);

    const int ngrid = (N_NODES + 255) / 256;         // 196
    const int egrid = (N_EDGES + 255) / 256;         // 6250
    const int sgrid = (N_NODES * 32 + 255) / 256;    // 6250 (1 warp/row)

    k_zero_nodes<<<ngrid, 256>>>();
    k_degree<<<egrid, 256>>>(src, dst, ew);
    k_norm<<<ngrid, 256>>>();
    k_scan1<<<SCAN_NB, SCAN_BS>>>();
    k_scan2<<<1, 128>>>();
    k_scan3<<<SCAN_NB, SCAN_BS>>>();
    k_fill<<<egrid, 256>>>(src, dst, ew);

    // Layer 1: T1, T2, T3 at F=128 (row stride 512 within Z1).
    // First spmm reads x directly and copies it into Z1 slice 0.
    k_spmm<4><<<sgrid, 256>>>(x,        128, Z1 + 128, 512, nullptr,   0, Z1, 512);
    k_spmm<4><<<sgrid, 256>>>(Z1 + 128, 512, Z1 + 256, 512, Z1,      512, nullptr, 0);
    k_spmm<4><<<sgrid, 256>>>(Z1 + 256, 512, Z1 + 384, 512, Z1 + 128, 512, nullptr, 0);

    // h = relu(Z1 @ W1 + b1) -> written directly into Z2 slice 0
    k_gemm<512, 64, true><<<148, 512, smem1>>>(Z1, 512, W1, b1, Z2, 256);

    // Layer 2: T1, T2, T3 at F=64 (row stride 256 within Z2)
    k_spmm<2><<<sgrid, 256>>>(Z2,       256, Z2 + 64,  256, nullptr,   0, nullptr, 0);
    k_spmm<2><<<sgrid, 256>>>(Z2 + 64,  256, Z2 + 128, 256, Z2,      256, nullptr, 0);
    k_spmm<2><<<sgrid, 256>>>(Z2 + 128, 256, Z2 + 192, 256, Z2 + 64, 256, nullptr, 0);

    // out = Z2 @ W2 + b2
    k_gemm<256, 40, false><<<148, 512, smem2>>>(Z2, 256, W2, b2,
                                                (float*)d_out, 40);
}

// round 4
// speedup vs baseline: 1.3848x; 1.1774x over previous
#include <cuda_runtime.h>
#include <cstdint>

// Problem constants (fixed shapes)
#define N_NODES 50000
#define N_EDGES 1600000

constexpr int SCAN_BS = 512;
constexpr int SCAN_NB = (N_NODES + SCAN_BS - 1) / SCAN_BS;  // 98

// ---------------------------------------------------------------------------
// Scratch
// ---------------------------------------------------------------------------
__device__ float g_deg[N_NODES];
__device__ float g_dis[N_NODES];
__device__ float g_diag[N_NODES];
__device__ int   g_cnt[N_NODES];
__device__ int   g_rowptr[N_NODES + 1];
__device__ int   g_cursor[N_NODES];
__device__ int   g_col[N_EDGES];
__device__ float g_w[N_EDGES];
__device__ int   g_bsum[SCAN_NB];
__device__ int   g_boff[SCAN_NB];
// Clenshaw buffers:
//   U = x @ [W1_0|W1_1|W1_2|W1_3]  (N x 256, slices of 64)
//   H = layer-1 output              (N x 64)
//   V = H @ [W2_0|W2_1|W2_2|W2_3]  (N x 160, slices of 40)
__device__ float g_U[(size_t)N_NODES * 256];
__device__ float g_H[(size_t)N_NODES * 64];
__device__ float g_V[(size_t)N_NODES * 160];

// ---------------------------------------------------------------------------
// Preprocessing
// ---------------------------------------------------------------------------
__global__ void k_zero_nodes() {
    int i = blockIdx.x * blockDim.x + threadIdx.x;
    if (i < N_NODES) { g_deg[i] = 0.f; g_cnt[i] = 0; }
}

__global__ void k_degree(const int* __restrict__ src, const int* __restrict__ dst,
                         const float* __restrict__ ew) {
    int e = blockIdx.x * blockDim.x + threadIdx.x;
    if (e < N_EDGES) {
        atomicAdd(&g_deg[src[e]], ew[e]);
        atomicAdd(&g_cnt[dst[e]], 1);
    }
}

__global__ void k_norm() {
    int i = blockIdx.x * blockDim.x + threadIdx.x;
    if (i < N_NODES) {
        float d = g_deg[i];
        g_dis[i]  = (d > 0.f) ? rsqrtf(fmaxf(d, 1e-12f)) : 0.f;
        g_diag[i] = (d > 0.f) ? 0.f : -1.f;
    }
}

// ---- 3-phase scan of g_cnt -> g_rowptr (exclusive), g_cursor ----
__global__ void k_scan1() {
    __shared__ int ws[SCAN_BS / 32];
    const int tid = threadIdx.x;
    const int i = blockIdx.x * SCAN_BS + tid;
    int v = (i < N_NODES) ? g_cnt[i] : 0;
#pragma unroll
    for (int off = 16; off > 0; off >>= 1)
        v += __shfl_down_sync(0xffffffffu, v, off);
    if ((tid & 31) == 0) ws[tid >> 5] = v;
    __syncthreads();
    if (tid < SCAN_BS / 32) {
        int s = ws[tid];
#pragma unroll
        for (int off = SCAN_BS / 64; off > 0; off >>= 1)
            s += __shfl_down_sync(0xffffffffu, s, off);
        if (tid == 0) g_bsum[blockIdx.x] = s;
    }
}

__global__ void k_scan2() {
    __shared__ int sm[128];
    const int tid = threadIdx.x;
    int v = (tid < SCAN_NB) ? g_bsum[tid] : 0;
    sm[tid] = v;
    __syncthreads();
#pragma unroll
    for (int off = 1; off < 128; off <<= 1) {
        int y = (tid >= off) ? sm[tid - off] : 0;
        __syncthreads();
        sm[tid] += y;
        __syncthreads();
    }
    if (tid < SCAN_NB) g_boff[tid] = sm[tid] - v;
    if (tid == 127) g_rowptr[N_NODES] = sm[127];
}

__global__ void k_scan3() {
    __shared__ int ws[SCAN_BS / 32];
    const int tid = threadIdx.x;
    const int lane = tid & 31;
    const int wid = tid >> 5;
    const int i = blockIdx.x * SCAN_BS + tid;
    int v = (i < N_NODES) ? g_cnt[i] : 0;
    int x = v;
#pragma unroll
    for (int off = 1; off < 32; off <<= 1) {
        int y = __shfl_up_sync(0xffffffffu, x, off);
        if (lane >= off) x += y;
    }
    if (lane == 31) ws[wid] = x;
    __syncthreads();
    if (wid == 0) {
        int s = (lane < SCAN_BS / 32) ? ws[lane] : 0;
#pragma unroll
        for (int off = 1; off < SCAN_BS / 32; off <<= 1) {
            int y = __shfl_up_sync(0xffffffffu, s, off);
            if (lane >= off) s += y;
        }
        if (lane < SCAN_BS / 32) ws[lane] = s;
    }
    __syncthreads();
    int excl = x - v + ((wid > 0) ? ws[wid - 1] : 0) + g_boff[blockIdx.x];
    if (i < N_NODES) { g_rowptr[i] = excl; g_cursor[i] = excl; }
}

__global__ void k_fill(const int* __restrict__ src, const int* __restrict__ dst,
                       const float* __restrict__ ew) {
    int e = blockIdx.x * blockDim.x + threadIdx.x;
    if (e < N_EDGES) {
        int s = src[e], d = dst[e];
        int pos = atomicAdd(&g_cursor[d], 1);
        g_col[pos] = s;
        g_w[pos] = -g_dis[s] * ew[e] * g_dis[d];
    }
}

// ---------------------------------------------------------------------------
// Clenshaw SpMM step: out = alpha * (L_hat @ in) + u [- v] [+ bias] [relu]
// One warp per row, float2 per lane, no shuffles (uniform col/w loads), x4
// unroll for gather MLP. FEATS in {64, 40}; for 40 only lanes 0..19 active.
// ---------------------------------------------------------------------------
template <int FEATS, bool HASV, bool HASBIAS, bool RELU>
__global__ __launch_bounds__(256) void k_spmm(
        const float* __restrict__ in, int si,
        const float* __restrict__ u, int su,
        const float* __restrict__ v, int sv,
        float alpha,
        float* __restrict__ out, int so,
        const float* __restrict__ bias) {
    const int lane = threadIdx.x & 31;
    const int row = (blockIdx.x * blockDim.x + threadIdx.x) >> 5;
    if (row >= N_NODES) return;
    const int lv = lane * 2;
    if (lv >= FEATS) return;

    const int beg = __ldg(&g_rowptr[row]);
    const int end = __ldg(&g_rowptr[row + 1]);

    float a0 = 0.f, a1 = 0.f;

    int e = beg;
    for (; e + 4 <= end; e += 4) {
        const int c0 = __ldg(&g_col[e + 0]);
        const int c1 = __ldg(&g_col[e + 1]);
        const int c2 = __ldg(&g_col[e + 2]);
        const int c3 = __ldg(&g_col[e + 3]);
        const float w0 = __ldg(&g_w[e + 0]);
        const float w1 = __ldg(&g_w[e + 1]);
        const float w2 = __ldg(&g_w[e + 2]);
        const float w3 = __ldg(&g_w[e + 3]);
        const float2 v0 = *(const float2*)(in + (size_t)c0 * si + lv);
        const float2 v1 = *(const float2*)(in + (size_t)c1 * si + lv);
        const float2 v2 = *(const float2*)(in + (size_t)c2 * si + lv);
        const float2 v3 = *(const float2*)(in + (size_t)c3 * si + lv);
        a0 = fmaf(w0, v0.x, a0); a1 = fmaf(w0, v0.y, a1);
        a0 = fmaf(w1, v1.x, a0); a1 = fmaf(w1, v1.y, a1);
        a0 = fmaf(w2, v2.x, a0); a1 = fmaf(w2, v2.y, a1);
        a0 = fmaf(w3, v3.x, a0); a1 = fmaf(w3, v3.y, a1);
    }
    for (; e < end; e++) {
        const int c = __ldg(&g_col[e]);
        const float w = __ldg(&g_w[e]);
        const float2 vv = *(const float2*)(in + (size_t)c * si + lv);
        a0 = fmaf(w, vv.x, a0); a1 = fmaf(w, vv.y, a1);
    }

    // diagonal term of L_hat
    {
        const float dg = g_diag[row];
        const float2 vd = *(const float2*)(in + (size_t)row * si + lv);
        a0 = fmaf(dg, vd.x, a0); a1 = fmaf(dg, vd.y, a1);
    }

    const float2 uu = *(const float2*)(u + (size_t)row * su + lv);
    float r0 = fmaf(alpha, a0, uu.x);
    float r1 = fmaf(alpha, a1, uu.y);
    if constexpr (HASV) {
        const float2 vv = *(const float2*)(v + (size_t)row * sv + lv);
        r0 -= vv.x; r1 -= vv.y;
    }
    if constexpr (HASBIAS) {
        r0 += bias[lv + 0];
        r1 += bias[lv + 1];
    }
    if constexpr (RELU) {
        r0 = fmaxf(r0, 0.f);
        r1 = fmaxf(r1, 0.f);
    }
    *(float2*)(out + (size_t)row * so + lv) = make_float2(r0, r1);
}

// ---------------------------------------------------------------------------
// GEMM: out[N x M] = A[N x KD] @ Wcat[KD x M]
// W given as NS stacked slices of (KD x SW); remapped into concatenated
// columns during the SMEM stage: Bs[kd][s*SW+j] = W[(s*KD+kd)*SW + j].
// Persistent grid-stride over row tiles, thread tile 4x4.
// ---------------------------------------------------------------------------
template <int KD, int M, int BM, int THREADS, int NS, int SW>
__global__ __launch_bounds__(THREADS) void k_gemm(
        const float* __restrict__ A, int lda,
        const float* __restrict__ W,
        float* __restrict__ out, int ldo) {
    constexpr int BK = 16;
    static_assert(THREADS == (M / 4) * (BM / 4), "thread mapping");
    extern __shared__ float sh[];
    float* Bs = sh;             // KD * M
    float* As = sh + KD * M;    // BK * BM, layout As[k][r]

    const int tid = threadIdx.x;

    // Stage W with slice remap
    for (int t = tid; t < KD * M / 4; t += THREADS) {
        const int flat = t * 4;
        const int kd = flat / M;
        const int c = flat - kd * M;
        const int s = c / SW;
        const int j = c - s * SW;
        const float4 val = *(const float4*)(W + ((size_t)(s * KD + kd)) * SW + j);
        *(float4*)(&Bs[(size_t)kd * M + c]) = val;
    }

    const int cx = tid % (M / 4);
    const int ry = tid / (M / 4);
    const int ntiles = (N_NODES + BM - 1) / BM;
    __syncthreads();

    for (int tile = blockIdx.x; tile < ntiles; tile += gridDim.x) {
        const int row0 = tile * BM;
        float acc[4][4];
#pragma unroll
        for (int j = 0; j < 4; j++)
#pragma unroll
            for (int i = 0; i < 4; i++) acc[j][i] = 0.f;

#pragma unroll 1
        for (int k0 = 0; k0 < KD; k0 += BK) {
            for (int t = tid; t < BM * BK / 4; t += THREADS) {
                const int kk4 = t & 3;
                const int r = t >> 2;
                const int row = row0 + r;
                float4 v = make_float4(0.f, 0.f, 0.f, 0.f);
                if (row < N_NODES)
                    v = *(const float4*)(A + (size_t)row * lda + k0 + kk4 * 4);
                As[(kk4 * 4 + 0) * BM + r] = v.x;
                As[(kk4 * 4 + 1) * BM + r] = v.y;
                As[(kk4 * 4 + 2) * BM + r] = v.z;
                As[(kk4 * 4 + 3) * BM + r] = v.w;
            }
            __syncthreads();
#pragma unroll
            for (int kk = 0; kk < BK; kk++) {
                const float4 aa = *(const float4*)(&As[kk * BM + ry * 4]);
                const float4 bb = *(const float4*)(&Bs[(size_t)(k0 + kk) * M + cx * 4]);
                acc[0][0] = fmaf(aa.x, bb.x, acc[0][0]);
                acc[0][1] = fmaf(aa.x, bb.y, acc[0][1]);
                acc[0][2] = fmaf(aa.x, bb.z, acc[0][2]);
                acc[0][3] = fmaf(aa.x, bb.w, acc[0][3]);
                acc[1][0] = fmaf(aa.y, bb.x, acc[1][0]);
                acc[1][1] = fmaf(aa.y, bb.y, acc[1][1]);
                acc[1][2] = fmaf(aa.y, bb.z, acc[1][2]);
                acc[1][3] = fmaf(aa.y, bb.w, acc[1][3]);
                acc[2][0] = fmaf(aa.z, bb.x, acc[2][0]);
                acc[2][1] = fmaf(aa.z, bb.y, acc[2][1]);
                acc[2][2] = fmaf(aa.z, bb.z, acc[2][2]);
                acc[2][3] = fmaf(aa.z, bb.w, acc[2][3]);
                acc[3][0] = fmaf(aa.w, bb.x, acc[3][0]);
                acc[3][1] = fmaf(aa.w, bb.y, acc[3][1]);
                acc[3][2] = fmaf(aa.w, bb.z, acc[3][2]);
                acc[3][3] = fmaf(aa.w, bb.w, acc[3][3]);
            }
            __syncthreads();
        }

        const int col = cx * 4;
#pragma unroll
        for (int j = 0; j < 4; j++) {
            const int row = row0 + ry * 4 + j;
            if (row < N_NODES) {
                *(float4*)(out + (size_t)row * ldo + col) =
                    make_float4(acc[j][0], acc[j][1], acc[j][2], acc[j][3]);
            }
        }
    }
}

// ---------------------------------------------------------------------------
// Launch
// ---------------------------------------------------------------------------
extern "C" void kernel_launch(void* const* d_in, const int* in_sizes, int n_in,
                              void* d_out, int out_size) {
    const float* x  = (const float*)d_in[0];
    const int*   ei = (const int*)d_in[1];
    const float* ew = (const float*)d_in[2];
    const float* W1 = (const float*)d_in[3];
    const float* b1 = (const float*)d_in[4];
    const float* W2 = (const float*)d_in[5];
    const float* b2 = (const float*)d_in[6];
    const int* src = ei;
    const int* dst = ei + N_EDGES;

    float *U, *H, *V;
    cudaGetSymbolAddress((void**)&U, g_U);
    cudaGetSymbolAddress((void**)&H, g_H);
    cudaGetSymbolAddress((void**)&V, g_V);

    // GEMM configs
    //  G1: U[N x 256] = x[N x 128] @ remap(W1)   (KD=128, M=256, BM=32, 512 thr)
    //  G2: V[N x 160] = H[N x 64]  @ remap(W2)   (KD=64,  M=160, BM=64, 640 thr)
    const int smem1 = (128 * 256 + 16 * 32) * 4;   // 133120 B
    const int smem2 = (64 * 160 + 16 * 64) * 4;    // 45056 B
    cudaFuncSetAttribute((const void*)k_gemm<128, 256, 32, 512, 4, 64>,
                         cudaFuncAttributeMaxDynamicSharedMemorySize, smem1);
    cudaFuncSetAttribute((const void*)k_gemm<64, 160, 64, 640, 4, 40>,
                         cudaFuncAttributeMaxDynamicSharedMemorySize, smem2);

    const int ngrid = (N_NODES + 255) / 256;
    const int egrid = (N_EDGES + 255) / 256;
    const int sgrid = (N_NODES * 32 + 255) / 256;  // 1 warp/row

    k_zero_nodes<<<ngrid, 256>>>();
    k_degree<<<egrid, 256>>>(src, dst, ew);
    k_norm<<<ngrid, 256>>>();
    k_scan1<<<SCAN_NB, SCAN_BS>>>();
    k_scan2<<<1, 128>>>();
    k_scan3<<<SCAN_NB, SCAN_BS>>>();
    k_fill<<<egrid, 256>>>(src, dst, ew);

    // ---- Layer 1 (Clenshaw at F=64) ----
    // U = x @ [W1_0|W1_1|W1_2|W1_3]
    k_gemm<128, 256, 32, 512, 4, 64><<<148, 512, smem1>>>(x, 128, W1, U, 256);
    float* U0 = U;        // slice 0
    float* U1 = U + 64;   // slice 1
    float* U2 = U + 128;  // slice 2
    float* U3 = U + 192;  // slice 3
    // b2 = 2*L@U3 + U2            (overwrites U2)
    k_spmm<64, false, false, false><<<sgrid, 256>>>(U3, 256, U2, 256, nullptr, 0,
                                                    2.f, U2, 256, nullptr);
    // b1 = 2*L@b2 + U1 - U3       (overwrites U1)
    k_spmm<64, true, false, false><<<sgrid, 256>>>(U2, 256, U1, 256, U3, 256,
                                                   2.f, U1, 256, nullptr);
    // H = relu(L@b1 + U0 - b2 + bias1)
    k_spmm<64, true, true, true><<<sgrid, 256>>>(U1, 256, U0, 256, U2, 256,
                                                 1.f, H, 64, b1);

    // ---- Layer 2 (Clenshaw at F=40) ----
    // V = H @ [W2_0|W2_1|W2_2|W2_3]
    k_gemm<64, 160, 64, 640, 4, 40><<<148, 640, smem2>>>(H, 64, W2, V, 160);
    float* V0 = V;        // slice 0
    float* V1 = V + 40;
    float* V2 = V + 80;
    float* V3 = V + 120;
    // c2 = 2*L@V3 + V2            (overwrites V2)
    k_spmm<40, false, false, false><<<sgrid, 256>>>(V3, 160, V2, 160, nullptr, 0,
                                                    2.f, V2, 160, nullptr);
    // c1 = 2*L@c2 + V1 - V3       (overwrites V1)
    k_spmm<40, true, false, false><<<sgrid, 256>>>(V2, 160, V1, 160, V3, 160,
                                                   2.f, V1, 160, nullptr);
    // out = L@c1 + V0 - c2 + bias2
    k_spmm<40, true, true, false><<<sgrid, 256>>>(V1, 160, V0, 160, V2, 160,
                                                  1.f, (float*)d_out, 40, b2);
}

// round 5
// speedup vs baseline: 1.5008x; 1.0838x over previous
#include <cuda_runtime.h>
#include <cstdint>

// Problem constants (fixed shapes)
#define N_NODES 50000
#define N_EDGES 1600000

constexpr int SCAN_BS = 512;
constexpr int SCAN_NB = (N_NODES + SCAN_BS - 1) / SCAN_BS;  // 98

// ---------------------------------------------------------------------------
// Scratch
// ---------------------------------------------------------------------------
__device__ float g_deg[N_NODES];
__device__ float g_dis[N_NODES];
__device__ float g_diag[N_NODES];
__device__ int   g_cnt[N_NODES];
__device__ int   g_rowptr[N_NODES + 1];
__device__ int   g_cursor[N_NODES];
__device__ int2  g_cw[N_EDGES];          // packed (col, w-bits)
__device__ int   g_bsum[SCAN_NB];
__device__ int   g_boff[SCAN_NB];
// Clenshaw buffers:
//   U = x @ [W1_0|W1_1|W1_2|W1_3]  (N x 256, slices of 64)
//   H = layer-1 output              (N x 64)
//   V = H @ [W2_0|W2_1|W2_2|W2_3]  (N x 160, slices of 40)
__device__ float g_U[(size_t)N_NODES * 256];
__device__ float g_H[(size_t)N_NODES * 64];
__device__ float g_V[(size_t)N_NODES * 160];

// ---------------------------------------------------------------------------
// Preprocessing
// ---------------------------------------------------------------------------
__global__ void k_zero_nodes() {
    int i = blockIdx.x * blockDim.x + threadIdx.x;
    if (i < N_NODES) { g_deg[i] = 0.f; g_cnt[i] = 0; }
}

__global__ void k_degree(const int* __restrict__ src, const int* __restrict__ dst,
                         const float* __restrict__ ew) {
    int e = blockIdx.x * blockDim.x + threadIdx.x;
    if (e < N_EDGES) {
        atomicAdd(&g_deg[src[e]], ew[e]);
        atomicAdd(&g_cnt[dst[e]], 1);
    }
}

__global__ void k_norm() {
    int i = blockIdx.x * blockDim.x + threadIdx.x;
    if (i < N_NODES) {
        float d = g_deg[i];
        g_dis[i]  = (d > 0.f) ? rsqrtf(fmaxf(d, 1e-12f)) : 0.f;
        g_diag[i] = (d > 0.f) ? 0.f : -1.f;
    }
}

// ---- 3-phase scan of g_cnt -> g_rowptr (exclusive), g_cursor ----
__global__ void k_scan1() {
    __shared__ int ws[SCAN_BS / 32];
    const int tid = threadIdx.x;
    const int i = blockIdx.x * SCAN_BS + tid;
    int v = (i < N_NODES) ? g_cnt[i] : 0;
#pragma unroll
    for (int off = 16; off > 0; off >>= 1)
        v += __shfl_down_sync(0xffffffffu, v, off);
    if ((tid & 31) == 0) ws[tid >> 5] = v;
    __syncthreads();
    if (tid < SCAN_BS / 32) {
        int s = ws[tid];
#pragma unroll
        for (int off = SCAN_BS / 64; off > 0; off >>= 1)
            s += __shfl_down_sync(0xffffffffu, s, off);
        if (tid == 0) g_bsum[blockIdx.x] = s;
    }
}

__global__ void k_scan2() {
    __shared__ int sm[128];
    const int tid = threadIdx.x;
    int v = (tid < SCAN_NB) ? g_bsum[tid] : 0;
    sm[tid] = v;
    __syncthreads();
#pragma unroll
    for (int off = 1; off < 128; off <<= 1) {
        int y = (tid >= off) ? sm[tid - off] : 0;
        __syncthreads();
        sm[tid] += y;
        __syncthreads();
    }
    if (tid < SCAN_NB) g_boff[tid] = sm[tid] - v;
    if (tid == 127) g_rowptr[N_NODES] = sm[127];
}

__global__ void k_scan3() {
    __shared__ int ws[SCAN_BS / 32];
    const int tid = threadIdx.x;
    const int lane = tid & 31;
    const int wid = tid >> 5;
    const int i = blockIdx.x * SCAN_BS + tid;
    int v = (i < N_NODES) ? g_cnt[i] : 0;
    int x = v;
#pragma unroll
    for (int off = 1; off < 32; off <<= 1) {
        int y = __shfl_up_sync(0xffffffffu, x, off);
        if (lane >= off) x += y;
    }
    if (lane == 31) ws[wid] = x;
    __syncthreads();
    if (wid == 0) {
        int s = (lane < SCAN_BS / 32) ? ws[lane] : 0;
#pragma unroll
        for (int off = 1; off < SCAN_BS / 32; off <<= 1) {
            int y = __shfl_up_sync(0xffffffffu, s, off);
            if (lane >= off) s += y;
        }
        if (lane < SCAN_BS / 32) ws[lane] = s;
    }
    __syncthreads();
    int excl = x - v + ((wid > 0) ? ws[wid - 1] : 0) + g_boff[blockIdx.x];
    if (i < N_NODES) { g_rowptr[i] = excl; g_cursor[i] = excl; }
}

__global__ void k_fill(const int* __restrict__ src, const int* __restrict__ dst,
                       const float* __restrict__ ew) {
    int e = blockIdx.x * blockDim.x + threadIdx.x;
    if (e < N_EDGES) {
        int s = src[e], d = dst[e];
        int pos = atomicAdd(&g_cursor[d], 1);
        float w = -g_dis[s] * ew[e] * g_dis[d];
        g_cw[pos] = make_int2(s, __float_as_int(w));
    }
}

// ---------------------------------------------------------------------------
// Clenshaw SpMM step: out = alpha * (L_hat @ in) + u [- v] [+ bias] [relu]
// Multi-row-per-warp: FEATS/4 lanes per row (float4/lane), 32/(FEATS/4) rows
// per warp. Packed (col,w) int2 loads. Loop to warp-max degree, predicated.
//   FEATS=64: 16 lanes/row, 2 rows/warp.  FEATS=40: 10 lanes/row, 3 rows/warp.
// ---------------------------------------------------------------------------
template <int FEATS, bool HASV, bool HASBIAS, bool RELU>
__global__ __launch_bounds__(256) void k_spmm(
        const float* __restrict__ in, int si,
        const float* __restrict__ u, int su,
        const float* __restrict__ v, int sv,
        float alpha,
        float* __restrict__ out, int so,
        const float* __restrict__ bias) {
    constexpr int LPR = FEATS / 4;   // lanes per row
    constexpr int RPW = 32 / LPR;    // rows per warp

    const int gw = (blockIdx.x * blockDim.x + threadIdx.x) >> 5;
    const int lane = threadIdx.x & 31;
    const int row_base = gw * RPW;
    if (row_base >= N_NODES) return;

    const int sub = lane / LPR;               // which row within warp
    const int li = lane % LPR;                // lane within row
    const int row_t = row_base + sub;
    const bool act = (sub < RPW) && (row_t < N_NODES);
    const int row = act ? row_t : 0;

    int beg = 0, deg = 0;
    if (act) {
        beg = __ldg(&g_rowptr[row]);
        deg = __ldg(&g_rowptr[row + 1]) - beg;
    }
    const int m = __reduce_max_sync(0xffffffffu, deg);
    const int lv = li * 4;

    float a0 = 0.f, a1 = 0.f, a2 = 0.f, a3 = 0.f;

    for (int j = 0; j < m; j += 4) {
        int c[4];
        float wt[4];
#pragma unroll
        for (int t = 0; t < 4; t++) {
            const bool ok = (j + t) < deg;
            int2 cwp = make_int2(0, 0);
            if (ok) cwp = __ldg(&g_cw[beg + j + t]);
            c[t] = cwp.x;
            wt[t] = __int_as_float(cwp.y);
        }
        float4 g0 = *(const float4*)(in + (size_t)c[0] * si + lv);
        float4 g1 = *(const float4*)(in + (size_t)c[1] * si + lv);
        float4 g2 = *(const float4*)(in + (size_t)c[2] * si + lv);
        float4 g3 = *(const float4*)(in + (size_t)c[3] * si + lv);
        a0 = fmaf(wt[0], g0.x, a0); a1 = fmaf(wt[0], g0.y, a1);
        a2 = fmaf(wt[0], g0.z, a2); a3 = fmaf(wt[0], g0.w, a3);
        a0 = fmaf(wt[1], g1.x, a0); a1 = fmaf(wt[1], g1.y, a1);
        a2 = fmaf(wt[1], g1.z, a2); a3 = fmaf(wt[1], g1.w, a3);
        a0 = fmaf(wt[2], g2.x, a0); a1 = fmaf(wt[2], g2.y, a1);
        a2 = fmaf(wt[2], g2.z, a2); a3 = fmaf(wt[2], g2.w, a3);
        a0 = fmaf(wt[3], g3.x, a0); a1 = fmaf(wt[3], g3.y, a1);
        a2 = fmaf(wt[3], g3.z, a2); a3 = fmaf(wt[3], g3.w, a3);
    }

    if (!act) return;

    // diagonal term of L_hat
    {
        const float dg = g_diag[row];
        const float4 vd = *(const float4*)(in + (size_t)row * si + lv);
        a0 = fmaf(dg, vd.x, a0); a1 = fmaf(dg, vd.y, a1);
        a2 = fmaf(dg, vd.z, a2); a3 = fmaf(dg, vd.w, a3);
    }

    const float4 uu = *(const float4*)(u + (size_t)row * su + lv);
    float r0 = fmaf(alpha, a0, uu.x);
    float r1 = fmaf(alpha, a1, uu.y);
    float r2 = fmaf(alpha, a2, uu.z);
    float r3 = fmaf(alpha, a3, uu.w);
    if constexpr (HASV) {
        const float4 vv = *(const float4*)(v + (size_t)row * sv + lv);
        r0 -= vv.x; r1 -= vv.y; r2 -= vv.z; r3 -= vv.w;
    }
    if constexpr (HASBIAS) {
        const float4 bb = *(const float4*)(bias + lv);
        r0 += bb.x; r1 += bb.y; r2 += bb.z; r3 += bb.w;
    }
    if constexpr (RELU) {
        r0 = fmaxf(r0, 0.f); r1 = fmaxf(r1, 0.f);
        r2 = fmaxf(r2, 0.f); r3 = fmaxf(r3, 0.f);
    }
    *(float4*)(out + (size_t)row * so + lv) = make_float4(r0, r1, r2, r3);
}

// ---------------------------------------------------------------------------
// GEMM: out[N x M] = A[N x KD] @ Wcat[KD x M]  (W slice-remapped into SMEM)
// ---------------------------------------------------------------------------
template <int KD, int M, int BM, int THREADS, int NS, int SW>
__global__ __launch_bounds__(THREADS) void k_gemm(
        const float* __restrict__ A, int lda,
        const float* __restrict__ W,
        float* __restrict__ out, int ldo) {
    constexpr int BK = 16;
    static_assert(THREADS == (M / 4) * (BM / 4), "thread mapping");
    extern __shared__ float sh[];
    float* Bs = sh;             // KD * M
    float* As = sh + KD * M;    // BK * BM, layout As[k][r]

    const int tid = threadIdx.x;

    for (int t = tid; t < KD * M / 4; t += THREADS) {
        const int flat = t * 4;
        const int kd = flat / M;
        const int c = flat - kd * M;
        const int s = c / SW;
        const int j = c - s * SW;
        const float4 val = *(const float4*)(W + ((size_t)(s * KD + kd)) * SW + j);
        *(float4*)(&Bs[(size_t)kd * M + c]) = val;
    }

    const int cx = tid % (M / 4);
    const int ry = tid / (M / 4);
    const int ntiles = (N_NODES + BM - 1) / BM;
    __syncthreads();

    for (int tile = blockIdx.x; tile < ntiles; tile += gridDim.x) {
        const int row0 = tile * BM;
        float acc[4][4];
#pragma unroll
        for (int j = 0; j < 4; j++)
#pragma unroll
            for (int i = 0; i < 4; i++) acc[j][i] = 0.f;

#pragma unroll 1
        for (int k0 = 0; k0 < KD; k0 += BK) {
            for (int t = tid; t < BM * BK / 4; t += THREADS) {
                const int kk4 = t & 3;
                const int r = t >> 2;
                const int row = row0 + r;
                float4 v = make_float4(0.f, 0.f, 0.f, 0.f);
                if (row < N_NODES)
                    v = *(const float4*)(A + (size_t)row * lda + k0 + kk4 * 4);
                As[(kk4 * 4 + 0) * BM + r] = v.x;
                As[(kk4 * 4 + 1) * BM + r] = v.y;
                As[(kk4 * 4 + 2) * BM + r] = v.z;
                As[(kk4 * 4 + 3) * BM + r] = v.w;
            }
            __syncthreads();
#pragma unroll
            for (int kk = 0; kk < BK; kk++) {
                const float4 aa = *(const float4*)(&As[kk * BM + ry * 4]);
                const float4 bb = *(const float4*)(&Bs[(size_t)(k0 + kk) * M + cx * 4]);
                acc[0][0] = fmaf(aa.x, bb.x, acc[0][0]);
                acc[0][1] = fmaf(aa.x, bb.y, acc[0][1]);
                acc[0][2] = fmaf(aa.x, bb.z, acc[0][2]);
                acc[0][3] = fmaf(aa.x, bb.w, acc[0][3]);
                acc[1][0] = fmaf(aa.y, bb.x, acc[1][0]);
                acc[1][1] = fmaf(aa.y, bb.y, acc[1][1]);
                acc[1][2] = fmaf(aa.y, bb.z, acc[1][2]);
                acc[1][3] = fmaf(aa.y, bb.w, acc[1][3]);
                acc[2][0] = fmaf(aa.z, bb.x, acc[2][0]);
                acc[2][1] = fmaf(aa.z, bb.y, acc[2][1]);
                acc[2][2] = fmaf(aa.z, bb.z, acc[2][2]);
                acc[2][3] = fmaf(aa.z, bb.w, acc[2][3]);
                acc[3][0] = fmaf(aa.w, bb.x, acc[3][0]);
                acc[3][1] = fmaf(aa.w, bb.y, acc[3][1]);
                acc[3][2] = fmaf(aa.w, bb.z, acc[3][2]);
                acc[3][3] = fmaf(aa.w, bb.w, acc[3][3]);
            }
            __syncthreads();
        }

        const int col = cx * 4;
#pragma unroll
        for (int j = 0; j < 4; j++) {
            const int row = row0 + ry * 4 + j;
            if (row < N_NODES) {
                *(float4*)(out + (size_t)row * ldo + col) =
                    make_float4(acc[j][0], acc[j][1], acc[j][2], acc[j][3]);
            }
        }
    }
}

// ---------------------------------------------------------------------------
// Launch
// ---------------------------------------------------------------------------
extern "C" void kernel_launch(void* const* d_in, const int* in_sizes, int n_in,
                              void* d_out, int out_size) {
    const float* x  = (const float*)d_in[0];
    const int*   ei = (const int*)d_in[1];
    const float* ew = (const float*)d_in[2];
    const float* W1 = (const float*)d_in[3];
    const float* b1 = (const float*)d_in[4];
    const float* W2 = (const float*)d_in[5];
    const float* b2 = (const float*)d_in[6];
    const int* src = ei;
    const int* dst = ei + N_EDGES;

    float *U, *H, *V;
    cudaGetSymbolAddress((void**)&U, g_U);
    cudaGetSymbolAddress((void**)&H, g_H);
    cudaGetSymbolAddress((void**)&V, g_V);

    const int smem1 = (128 * 256 + 16 * 32) * 4;   // 133120 B
    const int smem2 = (64 * 160 + 16 * 64) * 4;    // 45056 B
    cudaFuncSetAttribute((const void*)k_gemm<128, 256, 32, 512, 4, 64>,
                         cudaFuncAttributeMaxDynamicSharedMemorySize, smem1);
    cudaFuncSetAttribute((const void*)k_gemm<64, 160, 64, 640, 4, 40>,
                         cudaFuncAttributeMaxDynamicSharedMemorySize, smem2);

    const int ngrid = (N_NODES + 255) / 256;
    const int egrid = (N_EDGES + 255) / 256;
    // SpMM grids: warps = ceil(N / rows-per-warp)
    const int warps64 = (N_NODES + 1) / 2;            // RPW=2
    const int sgrid64 = (warps64 * 32 + 255) / 256;   // 3125
    const int warps40 = (N_NODES + 2) / 3;            // RPW=3
    const int sgrid40 = (warps40 * 32 + 255) / 256;   // 2084

    k_zero_nodes<<<ngrid, 256>>>();
    k_degree<<<egrid, 256>>>(src, dst, ew);
    k_norm<<<ngrid, 256>>>();
    k_scan1<<<SCAN_NB, SCAN_BS>>>();
    k_scan2<<<1, 128>>>();
    k_scan3<<<SCAN_NB, SCAN_BS>>>();
    k_fill<<<egrid, 256>>>(src, dst, ew);

    // ---- Layer 1 (Clenshaw at F=64) ----
    // U = x @ [W1_0|W1_1|W1_2|W1_3]
    k_gemm<128, 256, 32, 512, 4, 64><<<148, 512, smem1>>>(x, 128, W1, U, 256);
    float* U0 = U;
    float* U1 = U + 64;
    float* U2 = U + 128;
    float* U3 = U + 192;
    // b2c = 2*L@U3 + U2           (overwrites U2)
    k_spmm<64, false, false, false><<<sgrid64, 256>>>(U3, 256, U2, 256, nullptr, 0,
                                                      2.f, U2, 256, nullptr);
    // b1c = 2*L@b2c + U1 - U3     (overwrites U1)
    k_spmm<64, true, false, false><<<sgrid64, 256>>>(U2, 256, U1, 256, U3, 256,
                                                     2.f, U1, 256, nullptr);
    // H = relu(L@b1c + U0 - b2c + bias1)
    k_spmm<64, true, true, true><<<sgrid64, 256>>>(U1, 256, U0, 256, U2, 256,
                                                   1.f, H, 64, b1);

    // ---- Layer 2 (Clenshaw at F=40) ----
    // V = H @ [W2_0|W2_1|W2_2|W2_3]
    k_gemm<64, 160, 64, 640, 4, 40><<<148, 640, smem2>>>(H, 64, W2, V, 160);
    float* V0 = V;
    float* V1 = V + 40;
    float* V2 = V + 80;
    float* V3 = V + 120;
    // c2 = 2*L@V3 + V2            (overwrites V2)
    k_spmm<40, false, false, false><<<sgrid40, 256>>>(V3, 160, V2, 160, nullptr, 0,
                                                      2.f, V2, 160, nullptr);
    // c1 = 2*L@c2 + V1 - V3       (overwrites V1)
    k_spmm<40, true, false, false><<<sgrid40, 256>>>(V2, 160, V1, 160, V3, 160,
                                                     2.f, V1, 160, nullptr);
    // out = L@c1 + V0 - c2 + bias2
    k_spmm<40, true, true, false><<<sgrid40, 256>>>(V1, 160, V0, 160, V2, 160,
                                                    1.f, (float*)d_out, 40, b2);
}

// round 6
// speedup vs baseline: 1.7202x; 1.1462x over previous
#include <cuda_runtime.h>
#include <cstdint>

// Problem constants (fixed shapes)
#define N_NODES 50000
#define N_EDGES 1600000

constexpr int SCAN_BS = 512;
constexpr int SCAN_NB = (N_NODES + SCAN_BS - 1) / SCAN_BS;  // 98

// ---------------------------------------------------------------------------
// Scratch
// ---------------------------------------------------------------------------
__device__ float g_deg[N_NODES];
__device__ float g_dis[N_NODES];
__device__ float g_diag[N_NODES];
__device__ int   g_cnt[N_NODES];
__device__ int   g_rowptr[N_NODES + 1];
__device__ int   g_cursor[N_NODES];
__device__ int2  g_cw[N_EDGES];          // packed (col, w-bits)
__device__ int   g_bsum[SCAN_NB];
__device__ int   g_boff[SCAN_NB];
// Clenshaw buffers:
//   U = x @ [W1_0|W1_1|W1_2|W1_3]  (N x 256, slices of 64)
//   H = layer-1 output              (N x 64)
//   V = H @ [W2_0|W2_1|W2_2|W2_3]  (N x 160, slices of 40)
__device__ float g_U[(size_t)N_NODES * 256];
__device__ float g_H[(size_t)N_NODES * 64];
__device__ float g_V[(size_t)N_NODES * 160];

// ---------------------------------------------------------------------------
// Preprocessing
// ---------------------------------------------------------------------------
__global__ void k_zero_nodes() {
    int i = blockIdx.x * blockDim.x + threadIdx.x;
    if (i < N_NODES) { g_deg[i] = 0.f; g_cnt[i] = 0; }
}

__global__ void k_degree(const int* __restrict__ src, const int* __restrict__ dst,
                         const float* __restrict__ ew) {
    int e = blockIdx.x * blockDim.x + threadIdx.x;
    if (e < N_EDGES) {
        atomicAdd(&g_deg[src[e]], ew[e]);
        atomicAdd(&g_cnt[dst[e]], 1);
    }
}

__global__ void k_norm() {
    int i = blockIdx.x * blockDim.x + threadIdx.x;
    if (i < N_NODES) {
        float d = g_deg[i];
        g_dis[i]  = (d > 0.f) ? rsqrtf(fmaxf(d, 1e-12f)) : 0.f;
        g_diag[i] = (d > 0.f) ? 0.f : -1.f;
    }
}

// ---- 3-phase scan of g_cnt -> g_rowptr (exclusive), g_cursor ----
__global__ void k_scan1() {
    __shared__ int ws[SCAN_BS / 32];
    const int tid = threadIdx.x;
    const int i = blockIdx.x * SCAN_BS + tid;
    int v = (i < N_NODES) ? g_cnt[i] : 0;
#pragma unroll
    for (int off = 16; off > 0; off >>= 1)
        v += __shfl_down_sync(0xffffffffu, v, off);
    if ((tid & 31) == 0) ws[tid >> 5] = v;
    __syncthreads();
    if (tid < SCAN_BS / 32) {
        int s = ws[tid];
#pragma unroll
        for (int off = SCAN_BS / 64; off > 0; off >>= 1)
            s += __shfl_down_sync(0xffffffffu, s, off);
        if (tid == 0) g_bsum[blockIdx.x] = s;
    }
}

__global__ void k_scan2() {
    __shared__ int sm[128];
    const int tid = threadIdx.x;
    int v = (tid < SCAN_NB) ? g_bsum[tid] : 0;
    sm[tid] = v;
    __syncthreads();
#pragma unroll
    for (int off = 1; off < 128; off <<= 1) {
        int y = (tid >= off) ? sm[tid - off] : 0;
        __syncthreads();
        sm[tid] += y;
        __syncthreads();
    }
    if (tid < SCAN_NB) g_boff[tid] = sm[tid] - v;
    if (tid == 127) g_rowptr[N_NODES] = sm[127];
}

__global__ void k_scan3() {
    __shared__ int ws[SCAN_BS / 32];
    const int tid = threadIdx.x;
    const int lane = tid & 31;
    const int wid = tid >> 5;
    const int i = blockIdx.x * SCAN_BS + tid;
    int v = (i < N_NODES) ? g_cnt[i] : 0;
    int x = v;
#pragma unroll
    for (int off = 1; off < 32; off <<= 1) {
        int y = __shfl_up_sync(0xffffffffu, x, off);
        if (lane >= off) x += y;
    }
    if (lane == 31) ws[wid] = x;
    __syncthreads();
    if (wid == 0) {
        int s = (lane < SCAN_BS / 32) ? ws[lane] : 0;
#pragma unroll
        for (int off = 1; off < SCAN_BS / 32; off <<= 1) {
            int y = __shfl_up_sync(0xffffffffu, s, off);
            if (lane >= off) s += y;
        }
        if (lane < SCAN_BS / 32) ws[lane] = s;
    }
    __syncthreads();
    int excl = x - v + ((wid > 0) ? ws[wid - 1] : 0) + g_boff[blockIdx.x];
    if (i < N_NODES) { g_rowptr[i] = excl; g_cursor[i] = excl; }
}

__global__ void k_fill(const int* __restrict__ src, const int* __restrict__ dst,
                       const float* __restrict__ ew) {
    int e = blockIdx.x * blockDim.x + threadIdx.x;
    if (e < N_EDGES) {
        int s = src[e], d = dst[e];
        int pos = atomicAdd(&g_cursor[d], 1);
        float w = -g_dis[s] * ew[e] * g_dis[d];
        g_cw[pos] = make_int2(s, __float_as_int(w));
    }
}

// ---------------------------------------------------------------------------
// Clenshaw SpMM step: out = alpha * (L_hat @ in) + u [- v] [+ bias] [relu]
// Multi-row-per-warp: FEATS/4 lanes per row (float4/lane), 32/(FEATS/4) rows
// per warp. Packed (col,w) int2 loads. Loop to warp-max degree, predicated.
// ---------------------------------------------------------------------------
template <int FEATS, bool HASV, bool HASBIAS, bool RELU>
__global__ __launch_bounds__(256) void k_spmm(
        const float* __restrict__ in, int si,
        const float* __restrict__ u, int su,
        const float* __restrict__ v, int sv,
        float alpha,
        float* __restrict__ out, int so,
        const float* __restrict__ bias) {
    constexpr int LPR = FEATS / 4;   // lanes per row
    constexpr int RPW = 32 / LPR;    // rows per warp

    const int gw = (blockIdx.x * blockDim.x + threadIdx.x) >> 5;
    const int lane = threadIdx.x & 31;
    const int row_base = gw * RPW;
    if (row_base >= N_NODES) return;

    const int sub = lane / LPR;
    const int li = lane % LPR;
    const int row_t = row_base + sub;
    const bool act = (sub < RPW) && (row_t < N_NODES);
    const int row = act ? row_t : 0;

    int beg = 0, deg = 0;
    if (act) {
        beg = __ldg(&g_rowptr[row]);
        deg = __ldg(&g_rowptr[row + 1]) - beg;
    }
    const int m = __reduce_max_sync(0xffffffffu, deg);
    const int lv = li * 4;

    float a0 = 0.f, a1 = 0.f, a2 = 0.f, a3 = 0.f;

    for (int j = 0; j < m; j += 4) {
        int c[4];
        float wt[4];
#pragma unroll
        for (int t = 0; t < 4; t++) {
            const bool ok = (j + t) < deg;
            int2 cwp = make_int2(0, 0);
            if (ok) cwp = __ldg(&g_cw[beg + j + t]);
            c[t] = cwp.x;
            wt[t] = __int_as_float(cwp.y);
        }
        float4 g0 = *(const float4*)(in + (size_t)c[0] * si + lv);
        float4 g1 = *(const float4*)(in + (size_t)c[1] * si + lv);
        float4 g2 = *(const float4*)(in + (size_t)c[2] * si + lv);
        float4 g3 = *(const float4*)(in + (size_t)c[3] * si + lv);
        a0 = fmaf(wt[0], g0.x, a0); a1 = fmaf(wt[0], g0.y, a1);
        a2 = fmaf(wt[0], g0.z, a2); a3 = fmaf(wt[0], g0.w, a3);
        a0 = fmaf(wt[1], g1.x, a0); a1 = fmaf(wt[1], g1.y, a1);
        a2 = fmaf(wt[1], g1.z, a2); a3 = fmaf(wt[1], g1.w, a3);
        a0 = fmaf(wt[2], g2.x, a0); a1 = fmaf(wt[2], g2.y, a1);
        a2 = fmaf(wt[2], g2.z, a2); a3 = fmaf(wt[2], g2.w, a3);
        a0 = fmaf(wt[3], g3.x, a0); a1 = fmaf(wt[3], g3.y, a1);
        a2 = fmaf(wt[3], g3.z, a2); a3 = fmaf(wt[3], g3.w, a3);
    }

    if (!act) return;

    // diagonal term of L_hat
    {
        const float dg = g_diag[row];
        const float4 vd = *(const float4*)(in + (size_t)row * si + lv);
        a0 = fmaf(dg, vd.x, a0); a1 = fmaf(dg, vd.y, a1);
        a2 = fmaf(dg, vd.z, a2); a3 = fmaf(dg, vd.w, a3);
    }

    const float4 uu = *(const float4*)(u + (size_t)row * su + lv);
    float r0 = fmaf(alpha, a0, uu.x);
    float r1 = fmaf(alpha, a1, uu.y);
    float r2 = fmaf(alpha, a2, uu.z);
    float r3 = fmaf(alpha, a3, uu.w);
    if constexpr (HASV) {
        const float4 vv = *(const float4*)(v + (size_t)row * sv + lv);
        r0 -= vv.x; r1 -= vv.y; r2 -= vv.z; r3 -= vv.w;
    }
    if constexpr (HASBIAS) {
        const float4 bb = *(const float4*)(bias + lv);
        r0 += bb.x; r1 += bb.y; r2 += bb.z; r3 += bb.w;
    }
    if constexpr (RELU) {
        r0 = fmaxf(r0, 0.f); r1 = fmaxf(r1, 0.f);
        r2 = fmaxf(r2, 0.f); r3 = fmaxf(r3, 0.f);
    }
    *(float4*)(out + (size_t)row * so + lv) = make_float4(r0, r1, r2, r3);
}

// ---------------------------------------------------------------------------
// GEMM: out[N x M] = A[N x KD] @ Wcat[KD x M]  (W slice-remapped into SMEM)
// Thread tile 8x4: 32 FMA per 3 LDS.128 per k-step.
// ---------------------------------------------------------------------------
template <int KD, int M, int BM, int THREADS, int NS, int SW>
__global__ __launch_bounds__(THREADS) void k_gemm(
        const float* __restrict__ A, int lda,
        const float* __restrict__ W,
        float* __restrict__ out, int ldo) {
    constexpr int BK = 16;
    static_assert(THREADS == (M / 4) * (BM / 8), "thread mapping");
    extern __shared__ float sh[];
    float* Bs = sh;             // KD * M
    float* As = sh + KD * M;    // BK * BM, layout As[k][r]

    const int tid = threadIdx.x;

    // Stage W with slice remap: Bs[kd][s*SW+j] = W[(s*KD+kd)*SW + j]
    for (int t = tid; t < KD * M / 4; t += THREADS) {
        const int flat = t * 4;
        const int kd = flat / M;
        const int c = flat - kd * M;
        const int s = c / SW;
        const int j = c - s * SW;
        const float4 val = *(const float4*)(W + ((size_t)(s * KD + kd)) * SW + j);
        *(float4*)(&Bs[(size_t)kd * M + c]) = val;
    }

    const int cx = tid % (M / 4);
    const int ry = tid / (M / 4);     // 0 .. BM/8-1
    const int ntiles = (N_NODES + BM - 1) / BM;
    __syncthreads();

    for (int tile = blockIdx.x; tile < ntiles; tile += gridDim.x) {
        const int row0 = tile * BM;
        float acc[8][4];
#pragma unroll
        for (int j = 0; j < 8; j++)
#pragma unroll
            for (int i = 0; i < 4; i++) acc[j][i] = 0.f;

#pragma unroll 1
        for (int k0 = 0; k0 < KD; k0 += BK) {
            for (int t = tid; t < BM * BK / 4; t += THREADS) {
                const int kk4 = t & 3;
                const int r = t >> 2;
                const int row = row0 + r;
                float4 v = make_float4(0.f, 0.f, 0.f, 0.f);
                if (row < N_NODES)
                    v = *(const float4*)(A + (size_t)row * lda + k0 + kk4 * 4);
                As[(kk4 * 4 + 0) * BM + r] = v.x;
                As[(kk4 * 4 + 1) * BM + r] = v.y;
                As[(kk4 * 4 + 2) * BM + r] = v.z;
                As[(kk4 * 4 + 3) * BM + r] = v.w;
            }
            __syncthreads();
#pragma unroll
            for (int kk = 0; kk < BK; kk++) {
                const float4 aa0 = *(const float4*)(&As[kk * BM + ry * 8]);
                const float4 aa1 = *(const float4*)(&As[kk * BM + ry * 8 + 4]);
                const float4 bb = *(const float4*)(&Bs[(size_t)(k0 + kk) * M + cx * 4]);
                const float a[8] = {aa0.x, aa0.y, aa0.z, aa0.w,
                                    aa1.x, aa1.y, aa1.z, aa1.w};
#pragma unroll
                for (int j = 0; j < 8; j++) {
                    acc[j][0] = fmaf(a[j], bb.x, acc[j][0]);
                    acc[j][1] = fmaf(a[j], bb.y, acc[j][1]);
                    acc[j][2] = fmaf(a[j], bb.z, acc[j][2]);
                    acc[j][3] = fmaf(a[j], bb.w, acc[j][3]);
                }
            }
            __syncthreads();
        }

        const int col = cx * 4;
#pragma unroll
        for (int j = 0; j < 8; j++) {
            const int row = row0 + ry * 8 + j;
            if (row < N_NODES) {
                *(float4*)(out + (size_t)row * ldo + col) =
                    make_float4(acc[j][0], acc[j][1], acc[j][2], acc[j][3]);
            }
        }
    }
}

// ---------------------------------------------------------------------------
// Launch
// ---------------------------------------------------------------------------
extern "C" void kernel_launch(void* const* d_in, const int* in_sizes, int n_in,
                              void* d_out, int out_size) {
    const float* x  = (const float*)d_in[0];
    const int*   ei = (const int*)d_in[1];
    const float* ew = (const float*)d_in[2];
    const float* W1 = (const float*)d_in[3];
    const float* b1 = (const float*)d_in[4];
    const float* W2 = (const float*)d_in[5];
    const float* b2 = (const float*)d_in[6];
    const int* src = ei;
    const int* dst = ei + N_EDGES;

    float *U, *H, *V;
    cudaGetSymbolAddress((void**)&U, g_U);
    cudaGetSymbolAddress((void**)&H, g_H);
    cudaGetSymbolAddress((void**)&V, g_V);

    // GEMM configs (thread tile 8x4)
    //  G1: U[N x 256] = x[N x 128] @ remap(W1)   KD=128,M=256,BM=64,512 thr
    //  G2: V[N x 160] = H[N x 64]  @ remap(W2)   KD=64, M=160,BM=128,640 thr
    const int smem1 = (128 * 256 + 16 * 64) * 4;    // 135168 B
    const int smem2 = (64 * 160 + 16 * 128) * 4;    // 49152 B
    cudaFuncSetAttribute((const void*)k_gemm<128, 256, 64, 512, 4, 64>,
                         cudaFuncAttributeMaxDynamicSharedMemorySize, smem1);
    cudaFuncSetAttribute((const void*)k_gemm<64, 160, 128, 640, 4, 40>,
                         cudaFuncAttributeMaxDynamicSharedMemorySize, smem2);

    const int ngrid = (N_NODES + 255) / 256;
    const int egrid = (N_EDGES + 255) / 256;
    const int warps64 = (N_NODES + 1) / 2;            // RPW=2
    const int sgrid64 = (warps64 * 32 + 255) / 256;
    const int warps40 = (N_NODES + 2) / 3;            // RPW=3
    const int sgrid40 = (warps40 * 32 + 255) / 256;

    // --- Fork: preprocessing (CSR build) on s2, GEMM1 on main stream ---
    cudaStream_t s2;
    cudaEvent_t evFork, evJoin;
    cudaStreamCreateWithFlags(&s2, cudaStreamNonBlocking);
    cudaEventCreateWithFlags(&evFork, cudaEventDisableTiming);
    cudaEventCreateWithFlags(&evJoin, cudaEventDisableTiming);

    cudaEventRecord(evFork, 0);
    cudaStreamWaitEvent(s2, evFork, 0);

    k_zero_nodes<<<ngrid, 256, 0, s2>>>();
    k_degree<<<egrid, 256, 0, s2>>>(src, dst, ew);
    k_norm<<<ngrid, 256, 0, s2>>>();
    k_scan1<<<SCAN_NB, SCAN_BS, 0, s2>>>();
    k_scan2<<<1, 128, 0, s2>>>();
    k_scan3<<<SCAN_NB, SCAN_BS, 0, s2>>>();
    k_fill<<<egrid, 256, 0, s2>>>(src, dst, ew);
    cudaEventRecord(evJoin, s2);

    // GEMM1 concurrently on the main stream: U = x @ [W1 slices]
    k_gemm<128, 256, 64, 512, 4, 64><<<148, 512, smem1>>>(x, 128, W1, U, 256);

    cudaStreamWaitEvent(0, evJoin, 0);   // join before first SpMM

    float* U0 = U;
    float* U1 = U + 64;
    float* U2 = U + 128;
    float* U3 = U + 192;
    // ---- Layer 1 (Clenshaw at F=64) ----
    // b2c = 2*L@U3 + U2           (overwrites U2)
    k_spmm<64, false, false, false><<<sgrid64, 256>>>(U3, 256, U2, 256, nullptr, 0,
                                                      2.f, U2, 256, nullptr);
    // b1c = 2*L@b2c + U1 - U3     (overwrites U1)
    k_spmm<64, true, false, false><<<sgrid64, 256>>>(U2, 256, U1, 256, U3, 256,
                                                     2.f, U1, 256, nullptr);
    // H = relu(L@b1c + U0 - b2c + bias1)
    k_spmm<64, true, true, true><<<sgrid64, 256>>>(U1, 256, U0, 256, U2, 256,
                                                   1.f, H, 64, b1);

    // ---- Layer 2 (Clenshaw at F=40) ----
    // V = H @ [W2 slices]
    k_gemm<64, 160, 128, 640, 4, 40><<<148, 640, smem2>>>(H, 64, W2, V, 160);
    float* V0 = V;
    float* V1 = V + 40;
    float* V2 = V + 80;
    float* V3 = V + 120;
    // c2 = 2*L@V3 + V2            (overwrites V2)
    k_spmm<40, false, false, false><<<sgrid40, 256>>>(V3, 160, V2, 160, nullptr, 0,
                                                      2.f, V2, 160, nullptr);
    // c1 = 2*L@c2 + V1 - V3       (overwrites V1)
    k_spmm<40, true, false, false><<<sgrid40, 256>>>(V2, 160, V1, 160, V3, 160,
                                                     2.f, V1, 160, nullptr);
    // out = L@c1 + V0 - c2 + bias2
    k_spmm<40, true, true, false><<<sgrid40, 256>>>(V1, 160, V0, 160, V2, 160,
                                                    1.f, (float*)d_out, 40, b2);
}